// round 7
// baseline (speedup 1.0000x reference)
#include <cuda_runtime.h>
#include <math.h>

// ---------------- problem constants ----------------
#define BATCH 8
#define CCH   2
#define HF    128
#define INC   512
#define NPTS  128
#define NCAND 384
#define NIMP  96
#define NRAND 16
#define MROWS (BATCH*NPTS) // 1024
#define K1    514
#define K1P   528          // padded to multiple of 16
#define H1    512
#define H2    256

// ---------------- static scratch ----------------
__device__ float g_points[BATCH*NPTS*2];
__device__ float g_coarse[BATCH*CCH*NPTS];
__device__ float g_feat [MROWS*K1P];
__device__ float g_buf1 [MROWS*H1];     // raw (bias-added) GEMM1 output
__device__ float g_buf2 [MROWS*H2];     // raw (bias-added) GEMM2 output
__device__ float g_psum [MROWS*8];      // per-row partial sums (8 col-blocks)
__device__ float g_psqs [MROWS*8];      // per-row partial sum-of-squares

__device__ __forceinline__ unsigned int fenc(float v) {
    unsigned int u = __float_as_uint(v);
    return (u & 0x80000000u) ? ~u : (u | 0x80000000u);
}
__device__ __forceinline__ float gelu_exact(float y) {
    return 0.5f * y * (1.f + erff(y * 0.70710678118654752f));
}
__device__ __forceinline__ float warp_allred(float v) {
    #pragma unroll
    for (int o = 16; o > 0; o >>= 1) v += __shfl_xor_sync(0xFFFFFFFFu, v, o);
    return v;
}
__device__ __forceinline__ float half_allred(float v) {   // reduce within 16-lane group
    #pragma unroll
    for (int o = 8; o > 0; o >>= 1) v += __shfl_xor_sync(0xFFFFFFFFu, v, o);
    return v;
}

// packed f32x2 helpers (FFMA2 path — ptxas never emits this from C++)
__device__ __forceinline__ unsigned long long pack2(float lo, float hi) {
    unsigned long long r;
    asm("mov.b64 %0, {%1, %2};" : "=l"(r) : "f"(lo), "f"(hi));
    return r;
}
__device__ __forceinline__ void unpack2(unsigned long long v, float& lo, float& hi) {
    asm("mov.b64 {%0, %1}, %2;" : "=f"(lo), "=f"(hi) : "l"(v));
}
__device__ __forceinline__ void ffma2(unsigned long long& d,
                                      unsigned long long a, unsigned long long b) {
    asm("fma.rn.f32x2 %0, %1, %2, %0;" : "+l"(d) : "l"(a), "l"(b));
}

// =====================================================================
// Kernel 1: sampling-point selection
// =====================================================================
__global__ void k_points(const float* __restrict__ out,
                         const float* __restrict__ over_gen,
                         const float* __restrict__ rand_point,
                         float* __restrict__ pts_out, int write_out)
{
    int b = blockIdx.x;
    int t = threadIdx.x;
    __shared__ unsigned long long keys[NCAND];

    if (t < NCAND) {
        float px = over_gen[(b*NCAND + t)*2 + 0];
        float py = over_gen[(b*NCAND + t)*2 + 1];
        float gx = px * HF - 0.5f;
        float gy = py * HF - 0.5f;
        float x0f = floorf(gx), y0f = floorf(gy);
        float wx = gx - x0f, wy = gy - y0f;
        int x0 = (int)x0f, y0 = (int)y0f;
        const float* o0 = out + (size_t)b*CCH*HF*HF;
        const float* o1 = o0 + HF*HF;
        float unc = 0.f;
        #pragma unroll
        for (int dy = 0; dy < 2; dy++) {
            #pragma unroll
            for (int dx = 0; dx < 2; dx++) {
                int xi = x0 + dx, yi = y0 + dy;
                bool valid = (xi >= 0) && (xi < HF) && (yi >= 0) && (yi < HF);
                int xc = min(max(xi, 0), HF-1);
                int yc = min(max(yi, 0), HF-1);
                float a = __ldg(o0 + yc*HF + xc);
                float c = __ldg(o1 + yc*HF + xc);
                float w = (dx ? wx : 1.f - wx) * (dy ? wy : 1.f - wy);
                if (valid) unc += w * (fminf(a, c) - fmaxf(a, c));
            }
        }
        keys[t] = (((unsigned long long)fenc(unc)) << 32)
                | (unsigned long long)(1023 - t);
    }
    __syncthreads();

    if (t < NCAND) {
        unsigned long long mine = keys[t];
        int rank = 0;
        #pragma unroll 8
        for (int j = 0; j < NCAND; j++) rank += (keys[j] > mine);
        if (rank < NIMP) {
            float px = over_gen[(b*NCAND + t)*2 + 0];
            float py = over_gen[(b*NCAND + t)*2 + 1];
            g_points[(b*NPTS + rank)*2 + 0] = px;
            g_points[(b*NPTS + rank)*2 + 1] = py;
            if (write_out) {
                pts_out[(b*NPTS + rank)*2 + 0] = px;
                pts_out[(b*NPTS + rank)*2 + 1] = py;
            }
        }
    }
    if (t < NRAND) {
        int i = NIMP + t;
        int j = NIMP + NRAND + t;
        float rx = rand_point[(b*NRAND + t)*2 + 0];
        float ry = rand_point[(b*NRAND + t)*2 + 1];
        g_points[(b*NPTS + i)*2 + 0] = 0.f;
        g_points[(b*NPTS + i)*2 + 1] = 0.f;
        g_points[(b*NPTS + j)*2 + 0] = rx;
        g_points[(b*NPTS + j)*2 + 1] = ry;
        if (write_out) {
            pts_out[(b*NPTS + i)*2 + 0] = 0.f;
            pts_out[(b*NPTS + i)*2 + 1] = 0.f;
            pts_out[(b*NPTS + j)*2 + 0] = rx;
            pts_out[(b*NPTS + j)*2 + 1] = ry;
        }
    }
}

// =====================================================================
// Kernel 2: bilinear gather -> g_feat (row-major, padded to K1P, pad=0)
// =====================================================================
__global__ void k_gather(const float* __restrict__ res2,
                         const float* __restrict__ out)
{
    int n = blockIdx.x, b = blockIdx.y;
    int row = b*NPTS + n;
    float px = g_points[row*2 + 0];
    float py = g_points[row*2 + 1];
    float gx = px*HF - 0.5f, gy = py*HF - 0.5f;
    float x0f = floorf(gx), y0f = floorf(gy);
    float wx = gx - x0f, wy = gy - y0f;
    int x0 = (int)x0f, y0 = (int)y0f;
    int x1 = x0 + 1, y1 = y0 + 1;
    float vx0 = (x0 >= 0 && x0 < HF) ? 1.f : 0.f;
    float vx1 = (x1 >= 0 && x1 < HF) ? 1.f : 0.f;
    float vy0 = (y0 >= 0 && y0 < HF) ? 1.f : 0.f;
    float vy1 = (y1 >= 0 && y1 < HF) ? 1.f : 0.f;
    int xc0 = min(max(x0, 0), HF-1), xc1 = min(max(x1, 0), HF-1);
    int yc0 = min(max(y0, 0), HF-1), yc1 = min(max(y1, 0), HF-1);
    float w00 = (1.f-wx)*(1.f-wy)*vx0*vy0;
    float w10 = wx*(1.f-wy)*vx1*vy0;
    float w01 = (1.f-wx)*wy*vx0*vy1;
    float w11 = wx*wy*vx1*vy1;
    int i00 = yc0*HF + xc0, i10 = yc0*HF + xc1;
    int i01 = yc1*HF + xc0, i11 = yc1*HF + xc1;

    for (int k = threadIdx.x; k < K1P; k += blockDim.x) {
        float v = 0.f;
        if (k < CCH) {
            const float* p = out + ((size_t)(b*CCH + k))*HF*HF;
            v = w00*p[i00] + w10*p[i10] + w01*p[i01] + w11*p[i11];
            g_coarse[(b*CCH + k)*NPTS + n] = v;
        } else if (k < K1) {
            const float* p = res2 + ((size_t)(b*INC + (k - CCH)))*HF*HF;
            v = w00*__ldg(p+i00) + w10*__ldg(p+i10)
              + w01*__ldg(p+i01) + w11*__ldg(p+i11);
        }
        g_feat[(size_t)row*K1P + k] = v;
    }
}

// =====================================================================
// GEMM1 (FFMA2): C[1024,512] = feat @ w1 + b1 (raw), + per-row partial
// (sum, sumsq) over this block's 64 cols -> g_psum/g_psqs[row][bx].
// 64x64x16 tiles, 256 threads, TM=TN=4.
// =====================================================================
__global__ __launch_bounds__(256)
void sgemm1(const float* __restrict__ A, const float* __restrict__ B,
            const float* __restrict__ bias, float* __restrict__ C)
{
    __shared__ unsigned long long As2[16][64];          // (a,a) packed
    __shared__ __align__(16) float Bs[16][64];
    int tid = threadIdx.x;
    int bm = blockIdx.y * 64, bn = blockIdx.x * 64;
    int tx = tid & 15, ty = tid >> 4;

    int am = tid >> 2, akq = (tid & 3) << 2;
    int bkk = tid >> 4, bnq = (tid & 15) << 2;

    unsigned long long acc[4][2];
    #pragma unroll
    for (int i = 0; i < 4; i++) { acc[i][0] = 0ull; acc[i][1] = 0ull; }

    for (int k0 = 0; k0 < K1P; k0 += 16) {
        float4 av = *(const float4*)&A[(size_t)(bm + am)*K1P + k0 + akq];
        int gk = k0 + bkk;
        float4 bv = (gk < K1) ? *(const float4*)&B[(size_t)gk*H1 + bn + bnq]
                              : make_float4(0.f,0.f,0.f,0.f);
        As2[akq+0][am] = pack2(av.x, av.x);
        As2[akq+1][am] = pack2(av.y, av.y);
        As2[akq+2][am] = pack2(av.z, av.z);
        As2[akq+3][am] = pack2(av.w, av.w);
        *(float4*)&Bs[bkk][bnq] = bv;
        __syncthreads();
        #pragma unroll
        for (int kk = 0; kk < 16; kk++) {
            unsigned long long ra0 = As2[kk][ty*4+0];
            unsigned long long ra1 = As2[kk][ty*4+1];
            unsigned long long ra2 = As2[kk][ty*4+2];
            unsigned long long ra3 = As2[kk][ty*4+3];
            ulonglong2 rb = *(const ulonglong2*)&Bs[kk][tx*4];
            ffma2(acc[0][0], ra0, rb.x); ffma2(acc[0][1], ra0, rb.y);
            ffma2(acc[1][0], ra1, rb.x); ffma2(acc[1][1], ra1, rb.y);
            ffma2(acc[2][0], ra2, rb.x); ffma2(acc[2][1], ra2, rb.y);
            ffma2(acc[3][0], ra3, rb.x); ffma2(acc[3][1], ra3, rb.y);
        }
        __syncthreads();
    }

    float4 bb = *(const float4*)&bias[bn + tx*4];
    #pragma unroll
    for (int i = 0; i < 4; i++) {
        float c0, c1, c2, c3;
        unpack2(acc[i][0], c0, c1);
        unpack2(acc[i][1], c2, c3);
        c0 += bb.x; c1 += bb.y; c2 += bb.z; c3 += bb.w;
        int m = bm + ty*4 + i;
        float4 o; o.x = c0; o.y = c1; o.z = c2; o.w = c3;
        *(float4*)&C[(size_t)m*H1 + bn + tx*4] = o;
        // per-row partial stats over this block's 64 cols
        float s = half_allred(c0 + c1 + c2 + c3);
        float q = half_allred(c0*c0 + c1*c1 + c2*c2 + c3*c3);
        if (tx == 0) {
            g_psum[m*8 + blockIdx.x] = s;
            g_psqs[m*8 + blockIdx.x] = q;
        }
    }
}

// =====================================================================
// GEMM2 (FFMA2): A-load applies LN+GELU on the fly using precomputed
// row stats.  C[1024,256] = act(buf1) @ w2 + b2 (raw) -> g_buf2.
// 32x64x16 tiles, 256 threads, TM=2 TN=4.
// =====================================================================
__global__ __launch_bounds__(256)
void sgemm2(const float* __restrict__ A, const float* __restrict__ B,
            const float* __restrict__ bias,
            const float* __restrict__ gm1, const float* __restrict__ be1,
            float* __restrict__ C)
{
    __shared__ unsigned long long As2[16][32];
    __shared__ __align__(16) float Bs[16][64];
    __shared__ float s_mean[32], s_inv[32];
    int tid = threadIdx.x;
    int bm = blockIdx.y * 32, bn = blockIdx.x * 64;
    int tx = tid & 15, ty = tid >> 4;

    if (tid < 32) {
        int m = bm + tid;
        float4 p0 = *(const float4*)&g_psum[m*8 + 0];
        float4 p1 = *(const float4*)&g_psum[m*8 + 4];
        float4 q0 = *(const float4*)&g_psqs[m*8 + 0];
        float4 q1 = *(const float4*)&g_psqs[m*8 + 4];
        float s = p0.x+p0.y+p0.z+p0.w + p1.x+p1.y+p1.z+p1.w;
        float q = q0.x+q0.y+q0.z+q0.w + q1.x+q1.y+q1.z+q1.w;
        float mean = s * (1.f/H1);
        float var  = q * (1.f/H1) - mean*mean;
        s_mean[tid] = mean;
        s_inv[tid]  = rsqrtf(var + 1e-5f);
    }
    __syncthreads();

    int am = tid >> 2, akq = (tid & 3) << 2;   // tid<128 loads A
    int bkk = tid >> 4, bnq = (tid & 15) << 2;

    unsigned long long acc[2][2];
    acc[0][0] = acc[0][1] = acc[1][0] = acc[1][1] = 0ull;

    for (int k0 = 0; k0 < H1; k0 += 16) {
        if (tid < 128) {
            float4 av = *(const float4*)&A[(size_t)(bm + am)*H1 + k0 + akq];
            float4 gg = *(const float4*)&gm1[k0 + akq];
            float4 be = *(const float4*)&be1[k0 + akq];
            float mean = s_mean[am], inv = s_inv[am];
            float h0 = gelu_exact((av.x-mean)*inv*gg.x + be.x);
            float h1 = gelu_exact((av.y-mean)*inv*gg.y + be.y);
            float h2 = gelu_exact((av.z-mean)*inv*gg.z + be.z);
            float h3 = gelu_exact((av.w-mean)*inv*gg.w + be.w);
            As2[akq+0][am] = pack2(h0, h0);
            As2[akq+1][am] = pack2(h1, h1);
            As2[akq+2][am] = pack2(h2, h2);
            As2[akq+3][am] = pack2(h3, h3);
        }
        *(float4*)&Bs[bkk][bnq] = *(const float4*)&B[(size_t)(k0 + bkk)*H2 + bn + bnq];
        __syncthreads();
        #pragma unroll
        for (int kk = 0; kk < 16; kk++) {
            unsigned long long ra0 = As2[kk][ty*2+0];
            unsigned long long ra1 = As2[kk][ty*2+1];
            ulonglong2 rb = *(const ulonglong2*)&Bs[kk][tx*4];
            ffma2(acc[0][0], ra0, rb.x); ffma2(acc[0][1], ra0, rb.y);
            ffma2(acc[1][0], ra1, rb.x); ffma2(acc[1][1], ra1, rb.y);
        }
        __syncthreads();
    }

    float4 bb = *(const float4*)&bias[bn + tx*4];
    #pragma unroll
    for (int i = 0; i < 2; i++) {
        float c0, c1, c2, c3;
        unpack2(acc[i][0], c0, c1);
        unpack2(acc[i][1], c2, c3);
        int m = bm + ty*2 + i;
        float4 o;
        o.x = c0 + bb.x; o.y = c1 + bb.y; o.z = c2 + bb.z; o.w = c3 + bb.w;
        *(float4*)&C[(size_t)m*H2 + bn + tx*4] = o;
    }
}

// =====================================================================
// LN+GELU (D=256) + projection (256->2) + dropout + residual, warp/row
// =====================================================================
__global__ __launch_bounds__(256)
void ln_final(const float* __restrict__ gw, const float* __restrict__ bw,
              const float* __restrict__ w3, const float* __restrict__ b3,
              const float* __restrict__ mask, float* __restrict__ rend)
{
    int warp = threadIdx.x >> 5, lane = threadIdx.x & 31;
    int row = blockIdx.x * 8 + warp;
    const float* x = g_buf2 + (size_t)row * H2;
    float4 v[2];
    float s = 0.f;
    #pragma unroll
    for (int i = 0; i < 2; i++) {
        v[i] = *(const float4*)&x[i*128 + lane*4];
        s += v[i].x + v[i].y + v[i].z + v[i].w;
    }
    float mean = warp_allred(s) * (1.f/H2);
    float s2 = 0.f;
    #pragma unroll
    for (int i = 0; i < 2; i++) {
        float d0 = v[i].x-mean, d1 = v[i].y-mean, d2 = v[i].z-mean, d3 = v[i].w-mean;
        s2 += d0*d0 + d1*d1 + d2*d2 + d3*d3;
    }
    float inv = rsqrtf(warp_allred(s2) * (1.f/H2) + 1e-5f);
    float p0 = 0.f, p1 = 0.f;
    #pragma unroll
    for (int i = 0; i < 2; i++) {
        int c = i*128 + lane*4;
        float4 g = *(const float4*)&gw[c];
        float4 b = *(const float4*)&bw[c];
        float h0 = gelu_exact((v[i].x-mean)*inv*g.x + b.x);
        float h1 = gelu_exact((v[i].y-mean)*inv*g.y + b.y);
        float h2 = gelu_exact((v[i].z-mean)*inv*g.z + b.z);
        float h3 = gelu_exact((v[i].w-mean)*inv*g.w + b.w);
        float4 wA = *(const float4*)&w3[c*2];
        float4 wB = *(const float4*)&w3[c*2 + 4];
        p0 += h0*wA.x + h1*wA.z + h2*wB.x + h3*wB.z;
        p1 += h0*wA.y + h1*wA.w + h2*wB.y + h3*wB.w;
    }
    p0 = warp_allred(p0);
    p1 = warp_allred(p1);
    if (lane == 0) {
        int b = row >> 7, n = row & 127;
        int i0 = (b*CCH + 0)*NPTS + n;
        int i1 = (b*CCH + 1)*NPTS + n;
        rend[i0] = (p0 + b3[0]) * mask[i0] + g_coarse[i0];
        rend[i1] = (p1 + b3[1]) * mask[i1] + g_coarse[i1];
    }
}

// =====================================================================
extern "C" void kernel_launch(void* const* d_in, const int* in_sizes, int n_in,
                              void* d_out, int out_size)
{
    const float* res2       = (const float*)d_in[1];
    const float* out        = (const float*)d_in[2];
    const float* over_gen   = (const float*)d_in[3];
    const float* rand_point = (const float*)d_in[4];
    const float* mask       = (const float*)d_in[5];
    const float* w1  = (const float*)d_in[6];
    const float* b1  = (const float*)d_in[7];
    const float* gm1 = (const float*)d_in[8];
    const float* be1 = (const float*)d_in[9];
    const float* w2  = (const float*)d_in[10];
    const float* b2  = (const float*)d_in[11];
    const float* gm2 = (const float*)d_in[12];
    const float* be2 = (const float*)d_in[13];
    const float* w3  = (const float*)d_in[14];
    const float* b3  = (const float*)d_in[15];

    float* rend = (float*)d_out;
    int has_pts = (out_size >= BATCH*CCH*NPTS + BATCH*NPTS*2) ? 1 : 0;
    float* pts  = rend + BATCH*CCH*NPTS;

    float *p_feat, *p_buf1, *p_buf2;
    cudaGetSymbolAddress((void**)&p_feat, g_feat);
    cudaGetSymbolAddress((void**)&p_buf1, g_buf1);
    cudaGetSymbolAddress((void**)&p_buf2, g_buf2);

    k_points<<<BATCH, NCAND>>>(out, over_gen, rand_point, pts, has_pts);

    dim3 gg(NPTS, BATCH);
    k_gather<<<gg, 256>>>(res2, out);

    {   // [1024,528(514)] @ [514,512] + stats
        dim3 grid(H1/64, MROWS/64);
        sgemm1<<<grid, 256>>>(p_feat, w1, b1, p_buf1);
    }
    {   // LN+GELU fused into A-load; [1024,512] @ [512,256]
        dim3 grid(H2/64, MROWS/32);
        sgemm2<<<grid, 256>>>(p_buf1, w2, b2, gm1, be1, p_buf2);
    }
    ln_final<<<MROWS/8, 256>>>(gm2, be2, w3, b3, mask, rend);
}

// round 8
// speedup vs baseline: 1.0196x; 1.0196x over previous
#include <cuda_runtime.h>
#include <math.h>

// ---------------- problem constants ----------------
#define BATCH 8
#define CCH   2
#define HF    128
#define INC   512
#define NPTS  128
#define NCAND 384
#define NIMP  96
#define NRAND 16
#define MROWS (BATCH*NPTS) // 1024
#define K1    514
#define K1P   528          // padded to multiple of 16
#define H1    512
#define H2    256

// ---------------- static scratch ----------------
__device__ float g_points[BATCH*NPTS*2];
__device__ float g_coarse[BATCH*CCH*NPTS];
__device__ float g_feat [MROWS*K1P];
__device__ float g_buf1 [MROWS*H1];     // raw (bias-added) GEMM1 output
__device__ float g_buf2 [MROWS*H2];     // raw (bias-added) GEMM2 output
__device__ float g_psum [MROWS*8];      // per-row partial sums (8 col-blocks)
__device__ float g_psqs [MROWS*8];      // per-row partial sum-of-squares

__device__ __forceinline__ unsigned int fenc(float v) {
    unsigned int u = __float_as_uint(v);
    return (u & 0x80000000u) ? ~u : (u | 0x80000000u);
}
__device__ __forceinline__ float gelu_exact(float y) {
    return 0.5f * y * (1.f + erff(y * 0.70710678118654752f));
}
__device__ __forceinline__ float warp_allred(float v) {
    #pragma unroll
    for (int o = 16; o > 0; o >>= 1) v += __shfl_xor_sync(0xFFFFFFFFu, v, o);
    return v;
}
__device__ __forceinline__ float half_allred(float v) {   // reduce within 16-lane group
    #pragma unroll
    for (int o = 8; o > 0; o >>= 1) v += __shfl_xor_sync(0xFFFFFFFFu, v, o);
    return v;
}

// =====================================================================
// Kernel 1: sampling-point selection (exact lax.top_k(96) via rank count)
// =====================================================================
__global__ void k_points(const float* __restrict__ out,
                         const float* __restrict__ over_gen,
                         const float* __restrict__ rand_point,
                         float* __restrict__ pts_out, int write_out)
{
    int b = blockIdx.x;
    int t = threadIdx.x;
    __shared__ unsigned long long keys[NCAND];

    if (t < NCAND) {
        float px = over_gen[(b*NCAND + t)*2 + 0];
        float py = over_gen[(b*NCAND + t)*2 + 1];
        float gx = px * HF - 0.5f;
        float gy = py * HF - 0.5f;
        float x0f = floorf(gx), y0f = floorf(gy);
        float wx = gx - x0f, wy = gy - y0f;
        int x0 = (int)x0f, y0 = (int)y0f;
        const float* o0 = out + (size_t)b*CCH*HF*HF;
        const float* o1 = o0 + HF*HF;
        float unc = 0.f;
        #pragma unroll
        for (int dy = 0; dy < 2; dy++) {
            #pragma unroll
            for (int dx = 0; dx < 2; dx++) {
                int xi = x0 + dx, yi = y0 + dy;
                bool valid = (xi >= 0) && (xi < HF) && (yi >= 0) && (yi < HF);
                int xc = min(max(xi, 0), HF-1);
                int yc = min(max(yi, 0), HF-1);
                float a = __ldg(o0 + yc*HF + xc);
                float c = __ldg(o1 + yc*HF + xc);
                float w = (dx ? wx : 1.f - wx) * (dy ? wy : 1.f - wy);
                if (valid) unc += w * (fminf(a, c) - fmaxf(a, c));
            }
        }
        keys[t] = (((unsigned long long)fenc(unc)) << 32)
                | (unsigned long long)(1023 - t);
    }
    __syncthreads();

    if (t < NCAND) {
        unsigned long long mine = keys[t];
        int rank = 0;
        #pragma unroll 8
        for (int j = 0; j < NCAND; j++) rank += (keys[j] > mine);
        if (rank < NIMP) {
            float px = over_gen[(b*NCAND + t)*2 + 0];
            float py = over_gen[(b*NCAND + t)*2 + 1];
            g_points[(b*NPTS + rank)*2 + 0] = px;
            g_points[(b*NPTS + rank)*2 + 1] = py;
            if (write_out) {
                pts_out[(b*NPTS + rank)*2 + 0] = px;
                pts_out[(b*NPTS + rank)*2 + 1] = py;
            }
        }
    }
    if (t < NRAND) {
        int i = NIMP + t;
        int j = NIMP + NRAND + t;
        float rx = rand_point[(b*NRAND + t)*2 + 0];
        float ry = rand_point[(b*NRAND + t)*2 + 1];
        g_points[(b*NPTS + i)*2 + 0] = 0.f;
        g_points[(b*NPTS + i)*2 + 1] = 0.f;
        g_points[(b*NPTS + j)*2 + 0] = rx;
        g_points[(b*NPTS + j)*2 + 1] = ry;
        if (write_out) {
            pts_out[(b*NPTS + i)*2 + 0] = 0.f;
            pts_out[(b*NPTS + i)*2 + 1] = 0.f;
            pts_out[(b*NPTS + j)*2 + 0] = rx;
            pts_out[(b*NPTS + j)*2 + 1] = ry;
        }
    }
}

// =====================================================================
// Kernel 2: bilinear gather -> g_feat (row-major, padded to K1P, pad=0)
// =====================================================================
__global__ void k_gather(const float* __restrict__ res2,
                         const float* __restrict__ out)
{
    int n = blockIdx.x, b = blockIdx.y;
    int row = b*NPTS + n;
    float px = g_points[row*2 + 0];
    float py = g_points[row*2 + 1];
    float gx = px*HF - 0.5f, gy = py*HF - 0.5f;
    float x0f = floorf(gx), y0f = floorf(gy);
    float wx = gx - x0f, wy = gy - y0f;
    int x0 = (int)x0f, y0 = (int)y0f;
    int x1 = x0 + 1, y1 = y0 + 1;
    float vx0 = (x0 >= 0 && x0 < HF) ? 1.f : 0.f;
    float vx1 = (x1 >= 0 && x1 < HF) ? 1.f : 0.f;
    float vy0 = (y0 >= 0 && y0 < HF) ? 1.f : 0.f;
    float vy1 = (y1 >= 0 && y1 < HF) ? 1.f : 0.f;
    int xc0 = min(max(x0, 0), HF-1), xc1 = min(max(x1, 0), HF-1);
    int yc0 = min(max(y0, 0), HF-1), yc1 = min(max(y1, 0), HF-1);
    float w00 = (1.f-wx)*(1.f-wy)*vx0*vy0;
    float w10 = wx*(1.f-wy)*vx1*vy0;
    float w01 = (1.f-wx)*wy*vx0*vy1;
    float w11 = wx*wy*vx1*vy1;
    int i00 = yc0*HF + xc0, i10 = yc0*HF + xc1;
    int i01 = yc1*HF + xc0, i11 = yc1*HF + xc1;

    for (int k = threadIdx.x; k < K1P; k += blockDim.x) {
        float v = 0.f;
        if (k < CCH) {
            const float* p = out + ((size_t)(b*CCH + k))*HF*HF;
            v = w00*p[i00] + w10*p[i10] + w01*p[i01] + w11*p[i11];
            g_coarse[(b*CCH + k)*NPTS + n] = v;
        } else if (k < K1) {
            const float* p = res2 + ((size_t)(b*INC + (k - CCH)))*HF*HF;
            v = w00*__ldg(p+i00) + w10*__ldg(p+i10)
              + w01*__ldg(p+i01) + w11*__ldg(p+i11);
        }
        g_feat[(size_t)row*K1P + k] = v;
    }
}

// =====================================================================
// GEMM1 (scalar FFMA, R6 inner loop): C = feat @ w1 + b1 (raw) +
// per-row partial (sum,sumsq) over this block's 64 cols.
// 64x64x16 tiles, 256 threads, TM=TN=4, vectorized global ld/st.
// =====================================================================
__global__ __launch_bounds__(256)
void sgemm1(const float* __restrict__ A, const float* __restrict__ B,
            const float* __restrict__ bias, float* __restrict__ C)
{
    __shared__ float As[16][65];
    __shared__ float Bs[16][64];
    int tid = threadIdx.x;
    int bm = blockIdx.y * 64, bn = blockIdx.x * 64;
    int tx = tid & 15, ty = tid >> 4;

    int am = tid >> 2, akq = (tid & 3) << 2;
    int bkk = tid >> 4, bnq = (tid & 15) << 2;

    float acc[4][4];
    #pragma unroll
    for (int i = 0; i < 4; i++)
        #pragma unroll
        for (int j = 0; j < 4; j++) acc[i][j] = 0.f;

    for (int k0 = 0; k0 < K1P; k0 += 16) {
        float4 av = *(const float4*)&A[(size_t)(bm + am)*K1P + k0 + akq];
        int gk = k0 + bkk;
        float4 bv = (gk < K1) ? *(const float4*)&B[(size_t)gk*H1 + bn + bnq]
                              : make_float4(0.f,0.f,0.f,0.f);
        As[akq+0][am] = av.x; As[akq+1][am] = av.y;
        As[akq+2][am] = av.z; As[akq+3][am] = av.w;
        *(float4*)&Bs[bkk][bnq] = bv;
        __syncthreads();
        #pragma unroll
        for (int kk = 0; kk < 16; kk++) {
            float ra0 = As[kk][ty*4+0], ra1 = As[kk][ty*4+1];
            float ra2 = As[kk][ty*4+2], ra3 = As[kk][ty*4+3];
            float4 rb = *(const float4*)&Bs[kk][tx*4];
            acc[0][0] += ra0*rb.x; acc[0][1] += ra0*rb.y; acc[0][2] += ra0*rb.z; acc[0][3] += ra0*rb.w;
            acc[1][0] += ra1*rb.x; acc[1][1] += ra1*rb.y; acc[1][2] += ra1*rb.z; acc[1][3] += ra1*rb.w;
            acc[2][0] += ra2*rb.x; acc[2][1] += ra2*rb.y; acc[2][2] += ra2*rb.z; acc[2][3] += ra2*rb.w;
            acc[3][0] += ra3*rb.x; acc[3][1] += ra3*rb.y; acc[3][2] += ra3*rb.z; acc[3][3] += ra3*rb.w;
        }
        __syncthreads();
    }
    float4 bb = *(const float4*)&bias[bn + tx*4];
    #pragma unroll
    for (int i = 0; i < 4; i++) {
        float c0 = acc[i][0] + bb.x, c1 = acc[i][1] + bb.y;
        float c2 = acc[i][2] + bb.z, c3 = acc[i][3] + bb.w;
        int m = bm + ty*4 + i;
        float4 o; o.x = c0; o.y = c1; o.z = c2; o.w = c3;
        *(float4*)&C[(size_t)m*H1 + bn + tx*4] = o;
        // per-row partial stats over this block's 64 cols (16 lanes of same row)
        float s = half_allred(c0 + c1 + c2 + c3);
        float q = half_allred(c0*c0 + c1*c1 + c2*c2 + c3*c3);
        if (tx == 0) {
            g_psum[m*8 + blockIdx.x] = s;
            g_psqs[m*8 + blockIdx.x] = q;
        }
    }
}

// =====================================================================
// GEMM2 (scalar FFMA, R6 inner loop): A-load applies LN+GELU on the fly
// using sgemm1's row stats. C[1024,256] = act(buf1) @ w2 + b2 -> g_buf2.
// 32x64x16 tiles, 256 threads, TM=2 TN=4.
// =====================================================================
__global__ __launch_bounds__(256)
void sgemm2(const float* __restrict__ A, const float* __restrict__ B,
            const float* __restrict__ bias,
            const float* __restrict__ gm1, const float* __restrict__ be1,
            float* __restrict__ C)
{
    __shared__ float As[16][33];
    __shared__ float Bs[16][64];
    __shared__ float s_mean[32], s_inv[32];
    int tid = threadIdx.x;
    int bm = blockIdx.y * 32, bn = blockIdx.x * 64;
    int tx = tid & 15, ty = tid >> 4;

    if (tid < 32) {
        int m = bm + tid;
        float4 p0 = *(const float4*)&g_psum[m*8 + 0];
        float4 p1 = *(const float4*)&g_psum[m*8 + 4];
        float4 q0 = *(const float4*)&g_psqs[m*8 + 0];
        float4 q1 = *(const float4*)&g_psqs[m*8 + 4];
        float s = p0.x+p0.y+p0.z+p0.w + p1.x+p1.y+p1.z+p1.w;
        float q = q0.x+q0.y+q0.z+q0.w + q1.x+q1.y+q1.z+q1.w;
        float mean = s * (1.f/H1);
        float var  = q * (1.f/H1) - mean*mean;
        s_mean[tid] = mean;
        s_inv[tid]  = rsqrtf(var + 1e-5f);
    }
    __syncthreads();

    int am = tid >> 2, akq = (tid & 3) << 2;   // tid<128 loads A
    int bkk = tid >> 4, bnq = (tid & 15) << 2;

    float acc[2][4];
    #pragma unroll
    for (int i = 0; i < 2; i++)
        #pragma unroll
        for (int j = 0; j < 4; j++) acc[i][j] = 0.f;

    for (int k0 = 0; k0 < H1; k0 += 16) {
        if (tid < 128) {
            float4 av = *(const float4*)&A[(size_t)(bm + am)*H1 + k0 + akq];
            float4 gg = *(const float4*)&gm1[k0 + akq];
            float4 be = *(const float4*)&be1[k0 + akq];
            float mean = s_mean[am], inv = s_inv[am];
            As[akq+0][am] = gelu_exact((av.x-mean)*inv*gg.x + be.x);
            As[akq+1][am] = gelu_exact((av.y-mean)*inv*gg.y + be.y);
            As[akq+2][am] = gelu_exact((av.z-mean)*inv*gg.z + be.z);
            As[akq+3][am] = gelu_exact((av.w-mean)*inv*gg.w + be.w);
        }
        *(float4*)&Bs[bkk][bnq] = *(const float4*)&B[(size_t)(k0 + bkk)*H2 + bn + bnq];
        __syncthreads();
        #pragma unroll
        for (int kk = 0; kk < 16; kk++) {
            float ra0 = As[kk][ty*2+0], ra1 = As[kk][ty*2+1];
            float4 rb = *(const float4*)&Bs[kk][tx*4];
            acc[0][0] += ra0*rb.x; acc[0][1] += ra0*rb.y; acc[0][2] += ra0*rb.z; acc[0][3] += ra0*rb.w;
            acc[1][0] += ra1*rb.x; acc[1][1] += ra1*rb.y; acc[1][2] += ra1*rb.z; acc[1][3] += ra1*rb.w;
        }
        __syncthreads();
    }
    float4 bb = *(const float4*)&bias[bn + tx*4];
    #pragma unroll
    for (int i = 0; i < 2; i++) {
        int m = bm + ty*2 + i;
        float4 o;
        o.x = acc[i][0] + bb.x; o.y = acc[i][1] + bb.y;
        o.z = acc[i][2] + bb.z; o.w = acc[i][3] + bb.w;
        *(float4*)&C[(size_t)m*H2 + bn + tx*4] = o;
    }
}

// =====================================================================
// LN+GELU (D=256) + projection (256->2) + dropout + residual, warp/row
// =====================================================================
__global__ __launch_bounds__(256)
void ln_final(const float* __restrict__ gw, const float* __restrict__ bw,
              const float* __restrict__ w3, const float* __restrict__ b3,
              const float* __restrict__ mask, float* __restrict__ rend)
{
    int warp = threadIdx.x >> 5, lane = threadIdx.x & 31;
    int row = blockIdx.x * 8 + warp;
    const float* x = g_buf2 + (size_t)row * H2;
    float4 v[2];
    float s = 0.f;
    #pragma unroll
    for (int i = 0; i < 2; i++) {
        v[i] = *(const float4*)&x[i*128 + lane*4];
        s += v[i].x + v[i].y + v[i].z + v[i].w;
    }
    float mean = warp_allred(s) * (1.f/H2);
    float s2 = 0.f;
    #pragma unroll
    for (int i = 0; i < 2; i++) {
        float d0 = v[i].x-mean, d1 = v[i].y-mean, d2 = v[i].z-mean, d3 = v[i].w-mean;
        s2 += d0*d0 + d1*d1 + d2*d2 + d3*d3;
    }
    float inv = rsqrtf(warp_allred(s2) * (1.f/H2) + 1e-5f);
    float p0 = 0.f, p1 = 0.f;
    #pragma unroll
    for (int i = 0; i < 2; i++) {
        int c = i*128 + lane*4;
        float4 g = *(const float4*)&gw[c];
        float4 b = *(const float4*)&bw[c];
        float h0 = gelu_exact((v[i].x-mean)*inv*g.x + b.x);
        float h1 = gelu_exact((v[i].y-mean)*inv*g.y + b.y);
        float h2 = gelu_exact((v[i].z-mean)*inv*g.z + b.z);
        float h3 = gelu_exact((v[i].w-mean)*inv*g.w + b.w);
        float4 wA = *(const float4*)&w3[c*2];
        float4 wB = *(const float4*)&w3[c*2 + 4];
        p0 += h0*wA.x + h1*wA.z + h2*wB.x + h3*wB.z;
        p1 += h0*wA.y + h1*wA.w + h2*wB.y + h3*wB.w;
    }
    p0 = warp_allred(p0);
    p1 = warp_allred(p1);
    if (lane == 0) {
        int b = row >> 7, n = row & 127;
        int i0 = (b*CCH + 0)*NPTS + n;
        int i1 = (b*CCH + 1)*NPTS + n;
        rend[i0] = (p0 + b3[0]) * mask[i0] + g_coarse[i0];
        rend[i1] = (p1 + b3[1]) * mask[i1] + g_coarse[i1];
    }
}

// =====================================================================
extern "C" void kernel_launch(void* const* d_in, const int* in_sizes, int n_in,
                              void* d_out, int out_size)
{
    const float* res2       = (const float*)d_in[1];
    const float* out        = (const float*)d_in[2];
    const float* over_gen   = (const float*)d_in[3];
    const float* rand_point = (const float*)d_in[4];
    const float* mask       = (const float*)d_in[5];
    const float* w1  = (const float*)d_in[6];
    const float* b1  = (const float*)d_in[7];
    const float* gm1 = (const float*)d_in[8];
    const float* be1 = (const float*)d_in[9];
    const float* w2  = (const float*)d_in[10];
    const float* b2  = (const float*)d_in[11];
    const float* gm2 = (const float*)d_in[12];
    const float* be2 = (const float*)d_in[13];
    const float* w3  = (const float*)d_in[14];
    const float* b3  = (const float*)d_in[15];

    float* rend = (float*)d_out;
    int has_pts = (out_size >= BATCH*CCH*NPTS + BATCH*NPTS*2) ? 1 : 0;
    float* pts  = rend + BATCH*CCH*NPTS;

    float *p_feat, *p_buf1, *p_buf2;
    cudaGetSymbolAddress((void**)&p_feat, g_feat);
    cudaGetSymbolAddress((void**)&p_buf1, g_buf1);
    cudaGetSymbolAddress((void**)&p_buf2, g_buf2);

    k_points<<<BATCH, NCAND>>>(out, over_gen, rand_point, pts, has_pts);

    dim3 gg(NPTS, BATCH);
    k_gather<<<gg, 256>>>(res2, out);

    {   // [1024,528(514)] @ [514,512] + row stats
        dim3 grid(H1/64, MROWS/64);
        sgemm1<<<grid, 256>>>(p_feat, w1, b1, p_buf1);
    }
    {   // LN+GELU fused into A-load; [1024,512] @ [512,256]
        dim3 grid(H2/64, MROWS/32);
        sgemm2<<<grid, 256>>>(p_buf1, w2, b2, gm1, be1, p_buf2);
    }
    ln_final<<<MROWS/8, 256>>>(gm2, be2, w3, b3, mask, rend);
}